// round 2
// baseline (speedup 1.0000x reference)
#include <cuda_runtime.h>
#include <cstdint>

#define N_NODES 50000
#define N_EDGES 800000
#define D 96

// ---------------- device scratch (no allocations allowed) -------------------
__device__ int g_cnt[N_NODES];        // per-dst degree (histogram)
__device__ int g_rowptr[N_NODES + 1]; // CSR row pointers
__device__ int g_pos[N_NODES];        // scatter cursors (copy of rowptr)
__device__ int g_csr_src[N_EDGES];    // src node per CSR slot

// ---------------------------------------------------------------------------
// K0: zero histogram counters
// ---------------------------------------------------------------------------
__global__ void k_init() {
    int i = blockIdx.x * blockDim.x + threadIdx.x;
    if (i < N_NODES) g_cnt[i] = 0;
}

// ---------------------------------------------------------------------------
// K1: histogram of dst degrees
// ---------------------------------------------------------------------------
__global__ void k_hist(const int* __restrict__ ei) {
    int e = blockIdx.x * blockDim.x + threadIdx.x;
    if (e < N_EDGES) atomicAdd(&g_cnt[ei[N_EDGES + e]], 1);
}

// ---------------------------------------------------------------------------
// K2: single-block exclusive scan over g_cnt -> g_rowptr / g_pos
// ---------------------------------------------------------------------------
#define SCAN_T 1024
#define SCAN_ITEMS 4
__global__ __launch_bounds__(SCAN_T, 1) void k_scan() {
    __shared__ int warp_sums[33];
    const int tid = threadIdx.x;
    const int lane = tid & 31, wid = tid >> 5;
    int carry = 0;
    const int TILE = SCAN_T * SCAN_ITEMS;  // 4096
    for (int base = 0; base < N_NODES; base += TILE) {
        int idx = base + tid * SCAN_ITEMS;
        int v[SCAN_ITEMS];
        #pragma unroll
        for (int i = 0; i < SCAN_ITEMS; i++)
            v[i] = (idx + i < N_NODES) ? g_cnt[idx + i] : 0;
        int tsum = v[0] + v[1] + v[2] + v[3];

        // warp inclusive scan of per-thread sums
        int incl = tsum;
        #pragma unroll
        for (int off = 1; off < 32; off <<= 1) {
            int t = __shfl_up_sync(0xffffffffu, incl, off);
            if (lane >= off) incl += t;
        }
        if (lane == 31) warp_sums[wid] = incl;
        __syncthreads();
        if (wid == 0) {
            int ws = warp_sums[lane];
            int wincl = ws;
            #pragma unroll
            for (int off = 1; off < 32; off <<= 1) {
                int t = __shfl_up_sync(0xffffffffu, wincl, off);
                if (lane >= off) wincl += t;
            }
            warp_sums[lane] = wincl - ws;           // exclusive warp offsets
            if (lane == 31) warp_sums[32] = wincl;  // block total
        }
        __syncthreads();
        int excl = carry + warp_sums[wid] + (incl - tsum);
        #pragma unroll
        for (int i = 0; i < SCAN_ITEMS; i++) {
            if (idx + i < N_NODES) {
                g_rowptr[idx + i] = excl;
                g_pos[idx + i] = excl;
            }
            excl += v[i];
        }
        carry += warp_sums[32];
        __syncthreads();
    }
    if (tid == 0) g_rowptr[N_NODES] = carry;  // == N_EDGES
}

// ---------------------------------------------------------------------------
// K3: scatter edge src ids into CSR slots
// ---------------------------------------------------------------------------
__global__ void k_scatter(const int* __restrict__ ei) {
    int e = blockIdx.x * blockDim.x + threadIdx.x;
    if (e >= N_EDGES) return;
    int src = ei[e];
    int dst = ei[N_EDGES + e];
    int p = atomicAdd(&g_pos[dst], 1);
    g_csr_src[p] = src;
}

// ---------------------------------------------------------------------------
// K4: warp-per-node mean aggregation. out[node] = mean of x[src] rows.
//     Lane l owns columns l, l+32, l+64. No fp atomics, single store.
// ---------------------------------------------------------------------------
__global__ void k_agg(const float* __restrict__ x, float* __restrict__ out) {
    int gw = (blockIdx.x * blockDim.x + threadIdx.x) >> 5;
    if (gw >= N_NODES) return;
    int lane = threadIdx.x & 31;
    int beg = g_rowptr[gw];
    int end = g_rowptr[gw + 1];
    float a0 = 0.f, a1 = 0.f, a2 = 0.f;
    for (int j0 = beg; j0 < end; j0 += 32) {
        int n = end - j0; if (n > 32) n = 32;
        int s = (lane < n) ? g_csr_src[j0 + lane] : 0;
        for (int k = 0; k < n; k++) {
            int src = __shfl_sync(0xffffffffu, s, k);
            const float* row = x + (size_t)src * D;
            a0 += row[lane];
            a1 += row[lane + 32];
            a2 += row[lane + 64];
        }
    }
    int deg = end - beg;
    float inv = (deg > 0) ? 1.0f / (float)deg : 0.0f;
    float* o = out + (size_t)gw * D;
    o[lane]      = a0 * inv;
    o[lane + 32] = a1 * inv;
    o[lane + 64] = a2 * inv;
}

// ---------------------------------------------------------------------------
// K5: fused linear + ReLU using packed fma.rn.f32x2 (2 MACs per fma slot).
//     C[50000 x 96] = relu([agg_mean | x] @ [Wl;Wr]_cols + bl)
//     BM=128 rows, BN=96, BK=192. 192 threads: 16 row-groups x 12 col-groups,
//     TM=8 rows x TN=8 cols per thread (accs held as 4 f32x2 pairs per row).
// ---------------------------------------------------------------------------
constexpr int BM = 128;
constexpr int BN = 96;
constexpr int BK = 192;
constexpr int TM = 8;
constexpr int TN = 8;
constexpr int LTHREADS = (BM / TM) * (BN / TN);  // 192
constexpr int WPAD = 100;                        // floats per Ws row (16B-aligned)
constexpr int SMEM_FLOATS = BM * BK + BK * WPAD + BN;
constexpr size_t SMEM_BYTES = (size_t)SMEM_FLOATS * sizeof(float);  // 175,488

__device__ __forceinline__ unsigned long long dup2(float a) {
    unsigned long long r;
    asm("mov.b64 %0, {%1, %1};" : "=l"(r) : "f"(a));
    return r;
}
__device__ __forceinline__ void fma2(unsigned long long& d,
                                     unsigned long long a,
                                     unsigned long long b) {
    asm("fma.rn.f32x2 %0, %1, %2, %0;" : "+l"(d) : "l"(a), "l"(b));
}

__global__ __launch_bounds__(LTHREADS, 1)
void k_linear(const float* __restrict__ x,
              const float* __restrict__ Wl,
              const float* __restrict__ bl,
              const float* __restrict__ Wr,
              float* __restrict__ out)   // agg_mean on entry, z on exit
{
    extern __shared__ float smem[];
    float* As  = smem;                 // [BM][BK]
    float* Ws  = smem + BM * BK;       // [BK][WPAD]
    float* bls = Ws + BK * WPAD;       // [BN]

    const int t = threadIdx.x;
    const int rowBase = blockIdx.x * BM;

    // ---- stage W transposed: Ws[k][o] = (k<96 ? Wl : Wr)[o][k%96]
    for (int idx = t; idx < BK * BN; idx += LTHREADS) {
        int o = idx / BK;
        int k = idx - o * BK;
        float v = (k < D) ? Wl[o * D + k] : Wr[o * D + (k - D)];
        Ws[k * WPAD + o] = v;
    }
    if (t < BN) bls[t] = bl[t];

    // ---- stage A tile: cols [0,96) = agg_mean (from out), [96,192) = x
    for (int idx = t; idx < BM * (BK / 4); idx += LTHREADS) {
        int r = idx / (BK / 4);
        int q = idx - r * (BK / 4);
        int node = rowBase + r;
        float4 v = make_float4(0.f, 0.f, 0.f, 0.f);
        if (node < N_NODES) {
            if (q < D / 4)
                v = *reinterpret_cast<const float4*>(out + (size_t)node * D + q * 4);
            else
                v = *reinterpret_cast<const float4*>(x + (size_t)node * D + (q - D / 4) * 4);
        }
        *reinterpret_cast<float4*>(As + r * BK + q * 4) = v;
    }
    __syncthreads();

    const int cg = t % (BN / TN);   // 0..11
    const int rg = t / (BN / TN);   // 0..15
    const int o0 = cg * TN;
    const int n0 = rg * TM;

    unsigned long long acc[TM][TN / 2];
    {
        const ulonglong2 b01 = *reinterpret_cast<const ulonglong2*>(bls + o0);
        const ulonglong2 b23 = *reinterpret_cast<const ulonglong2*>(bls + o0 + 4);
        #pragma unroll
        for (int i = 0; i < TM; i++) {
            acc[i][0] = b01.x; acc[i][1] = b01.y;
            acc[i][2] = b23.x; acc[i][3] = b23.y;
        }
    }

    for (int k = 0; k < BK; k += 4) {
        float4 av[TM];
        #pragma unroll
        for (int i = 0; i < TM; i++)
            av[i] = *reinterpret_cast<const float4*>(As + (n0 + i) * BK + k);
        #pragma unroll
        for (int kk = 0; kk < 4; kk++) {
            const ulonglong2 w01 =
                *reinterpret_cast<const ulonglong2*>(Ws + (k + kk) * WPAD + o0);
            const ulonglong2 w23 =
                *reinterpret_cast<const ulonglong2*>(Ws + (k + kk) * WPAD + o0 + 4);
            #pragma unroll
            for (int i = 0; i < TM; i++) {
                float a = (kk == 0) ? av[i].x : (kk == 1) ? av[i].y
                        : (kk == 2) ? av[i].z : av[i].w;
                unsigned long long ap = dup2(a);
                fma2(acc[i][0], ap, w01.x);
                fma2(acc[i][1], ap, w01.y);
                fma2(acc[i][2], ap, w23.x);
                fma2(acc[i][3], ap, w23.y);
            }
        }
    }

    // ---- epilogue: unpack, ReLU, store
    #pragma unroll
    for (int i = 0; i < TM; i++) {
        int node = rowBase + n0 + i;
        if (node >= N_NODES) continue;
        float r[TN];
        #pragma unroll
        for (int j = 0; j < TN / 2; j++) {
            float lo, hi;
            asm("mov.b64 {%0, %1}, %2;" : "=f"(lo), "=f"(hi) : "l"(acc[i][j]));
            r[2 * j]     = fmaxf(lo, 0.f);
            r[2 * j + 1] = fmaxf(hi, 0.f);
        }
        float4* dst = reinterpret_cast<float4*>(out + (size_t)node * D + o0);
        dst[0] = make_float4(r[0], r[1], r[2], r[3]);
        dst[1] = make_float4(r[4], r[5], r[6], r[7]);
    }
}

// ---------------------------------------------------------------------------
extern "C" void kernel_launch(void* const* d_in, const int* in_sizes, int n_in,
                              void* d_out, int out_size) {
    const float* x  = (const float*)d_in[0];   // [N, 96]
    const int* ei   = (const int*)d_in[1];     // [2, E]
    const float* Wl = (const float*)d_in[2];   // [96, 96]
    const float* bl = (const float*)d_in[3];   // [96]
    const float* Wr = (const float*)d_in[4];   // [96, 96]
    float* out = (float*)d_out;                // [N, 96]

    cudaFuncSetAttribute(k_linear, cudaFuncAttributeMaxDynamicSharedMemorySize,
                         (int)SMEM_BYTES);

    k_init<<<(N_NODES + 255) / 256, 256>>>();
    k_hist<<<(N_EDGES + 255) / 256, 256>>>(ei);
    k_scan<<<1, SCAN_T>>>();
    k_scatter<<<(N_EDGES + 255) / 256, 256>>>(ei);
    {
        int warps_per_block = 8;               // 256 threads
        int blocks = (N_NODES + warps_per_block - 1) / warps_per_block;
        k_agg<<<blocks, warps_per_block * 32>>>(x, out);
    }
    k_linear<<<(N_NODES + BM - 1) / BM, LTHREADS, SMEM_BYTES>>>(x, Wl, bl, Wr, out);
}

// round 4
// speedup vs baseline: 1.2662x; 1.2662x over previous
#include <cuda_runtime.h>
#include <cstdint>

#define N_NODES 50000
#define N_EDGES 800000
#define D 96

// ---------------- device scratch (no allocations allowed) -------------------
__device__ int g_cnt[N_NODES];        // per-dst degree (histogram)
__device__ int g_rowptr[N_NODES + 1]; // CSR row pointers
__device__ int g_rank[N_EDGES];       // within-dst rank of each edge
__device__ int g_csr_src[N_EDGES];    // src node per CSR slot

// ---------------------------------------------------------------------------
// K1: histogram of dst degrees; atomicAdd return value = rank of edge in dst
// ---------------------------------------------------------------------------
__global__ void k_hist(const int* __restrict__ ei) {
    int e = blockIdx.x * blockDim.x + threadIdx.x;
    if (e >= N_EDGES) return;
    int dst = ei[N_EDGES + e];
    g_rank[e] = atomicAdd(&g_cnt[dst], 1);
}

// ---------------------------------------------------------------------------
// K2: single-block exclusive scan over g_cnt -> g_rowptr
// ---------------------------------------------------------------------------
#define SCAN_T 1024
#define SCAN_ITEMS 4
__global__ __launch_bounds__(SCAN_T, 1) void k_scan() {
    __shared__ int warp_sums[33];
    const int tid = threadIdx.x;
    const int lane = tid & 31, wid = tid >> 5;
    int carry = 0;
    const int TILE = SCAN_T * SCAN_ITEMS;  // 4096
    for (int base = 0; base < N_NODES; base += TILE) {
        int idx = base + tid * SCAN_ITEMS;
        int v[SCAN_ITEMS];
        #pragma unroll
        for (int i = 0; i < SCAN_ITEMS; i++)
            v[i] = (idx + i < N_NODES) ? g_cnt[idx + i] : 0;
        int tsum = v[0] + v[1] + v[2] + v[3];

        int incl = tsum;
        #pragma unroll
        for (int off = 1; off < 32; off <<= 1) {
            int t = __shfl_up_sync(0xffffffffu, incl, off);
            if (lane >= off) incl += t;
        }
        if (lane == 31) warp_sums[wid] = incl;
        __syncthreads();
        if (wid == 0) {
            int ws = warp_sums[lane];
            int wincl = ws;
            #pragma unroll
            for (int off = 1; off < 32; off <<= 1) {
                int t = __shfl_up_sync(0xffffffffu, wincl, off);
                if (lane >= off) wincl += t;
            }
            warp_sums[lane] = wincl - ws;
            if (lane == 31) warp_sums[32] = wincl;
        }
        __syncthreads();
        int excl = carry + warp_sums[wid] + (incl - tsum);
        #pragma unroll
        for (int i = 0; i < SCAN_ITEMS; i++) {
            if (idx + i < N_NODES) g_rowptr[idx + i] = excl;
            excl += v[i];
        }
        carry += warp_sums[32];
        __syncthreads();
    }
    if (tid == 0) g_rowptr[N_NODES] = carry;
}

// ---------------------------------------------------------------------------
// K3: atomic-free scatter: slot = rowptr[dst] + rank[e]
// ---------------------------------------------------------------------------
__global__ void k_scatter(const int* __restrict__ ei) {
    int e = blockIdx.x * blockDim.x + threadIdx.x;
    if (e >= N_EDGES) return;
    int dst = ei[N_EDGES + e];
    int p = g_rowptr[dst] + g_rank[e];
    g_csr_src[p] = ei[e];
}

// ---------------------------------------------------------------------------
// K4: warp-per-node mean aggregation, neighbors unrolled by 4 (12 independent
//     loads in flight), dual accumulator banks. Lane l owns cols l,l+32,l+64.
// ---------------------------------------------------------------------------
__global__ void k_agg(const float* __restrict__ x, float* __restrict__ out) {
    int gw = (blockIdx.x * blockDim.x + threadIdx.x) >> 5;
    if (gw >= N_NODES) return;
    int lane = threadIdx.x & 31;
    int beg = g_rowptr[gw];
    int end = g_rowptr[gw + 1];

    float a0 = 0.f, a1 = 0.f, a2 = 0.f;   // bank A (even srcs)
    float b0 = 0.f, b1 = 0.f, b2 = 0.f;   // bank B (odd srcs)

    int j = beg;
    for (; j + 4 <= end; j += 4) {
        int s0 = g_csr_src[j + 0];
        int s1 = g_csr_src[j + 1];
        int s2 = g_csr_src[j + 2];
        int s3 = g_csr_src[j + 3];
        const float* r0 = x + (size_t)s0 * D;
        const float* r1 = x + (size_t)s1 * D;
        const float* r2 = x + (size_t)s2 * D;
        const float* r3 = x + (size_t)s3 * D;
        float v00 = r0[lane], v01 = r0[lane + 32], v02 = r0[lane + 64];
        float v10 = r1[lane], v11 = r1[lane + 32], v12 = r1[lane + 64];
        float v20 = r2[lane], v21 = r2[lane + 32], v22 = r2[lane + 64];
        float v30 = r3[lane], v31 = r3[lane + 32], v32 = r3[lane + 64];
        a0 += v00; a1 += v01; a2 += v02;
        b0 += v10; b1 += v11; b2 += v12;
        a0 += v20; a1 += v21; a2 += v22;
        b0 += v30; b1 += v31; b2 += v32;
    }
    for (; j < end; j++) {
        int s = g_csr_src[j];
        const float* r = x + (size_t)s * D;
        a0 += r[lane]; a1 += r[lane + 32]; a2 += r[lane + 64];
    }
    a0 += b0; a1 += b1; a2 += b2;

    int deg = end - beg;
    float inv = (deg > 0) ? 1.0f / (float)deg : 0.0f;
    float* o = out + (size_t)gw * D;
    o[lane]      = a0 * inv;
    o[lane + 32] = a1 * inv;
    o[lane + 64] = a2 * inv;
}

// ---------------------------------------------------------------------------
// K5: fused linear + ReLU with packed fma.rn.f32x2.
//     C[50000 x 96] = relu([agg_mean | x] @ [Wl;Wr]_cols + bl)
//     BM=128, BN=96, BK=192. 256 threads = 16 rowgroups x 16 colgroups,
//     TM=8 rows x TN=6 cols per thread (3 f32x2 acc pairs per row).
// ---------------------------------------------------------------------------
constexpr int BM = 128;
constexpr int BN = 96;
constexpr int BK = 192;
constexpr int TM = 8;
constexpr int TN = 6;
constexpr int LTHREADS = (BM / TM) * (BN / TN);  // 256
constexpr int WPAD = 98;                         // even -> 8B-aligned rows
constexpr int SMEM_FLOATS = BM * BK + BK * WPAD + BN;
constexpr size_t SMEM_BYTES = (size_t)SMEM_FLOATS * sizeof(float);  // ~173.6 KB

__device__ __forceinline__ unsigned long long dup2(float a) {
    unsigned long long r;
    asm("mov.b64 %0, {%1, %1};" : "=l"(r) : "f"(a));
    return r;
}
__device__ __forceinline__ void fma2(unsigned long long& d,
                                     unsigned long long a,
                                     unsigned long long b) {
    asm("fma.rn.f32x2 %0, %1, %2, %0;" : "+l"(d) : "l"(a), "l"(b));
}

__global__ __launch_bounds__(LTHREADS, 1)
void k_linear(const float* __restrict__ x,
              const float* __restrict__ Wl,
              const float* __restrict__ bl,
              const float* __restrict__ Wr,
              float* __restrict__ out)   // agg_mean on entry, z on exit
{
    extern __shared__ float smem[];
    float* As  = smem;                 // [BM][BK]
    float* Ws  = smem + BM * BK;       // [BK][WPAD]
    float* bls = Ws + BK * WPAD;       // [BN]

    const int t = threadIdx.x;
    const int rowBase = blockIdx.x * BM;

    // ---- stage W transposed: Ws[k][o] = (k<96 ? Wl : Wr)[o][k%96]
    for (int idx = t; idx < BK * BN; idx += LTHREADS) {
        int o = idx / BK;
        int k = idx - o * BK;
        float v = (k < D) ? Wl[o * D + k] : Wr[o * D + (k - D)];
        Ws[k * WPAD + o] = v;
    }
    if (t < BN) bls[t] = bl[t];

    // ---- stage A tile: cols [0,96) = agg_mean (from out), [96,192) = x
    for (int idx = t; idx < BM * (BK / 4); idx += LTHREADS) {
        int r = idx / (BK / 4);
        int q = idx - r * (BK / 4);
        int node = rowBase + r;
        float4 v = make_float4(0.f, 0.f, 0.f, 0.f);
        if (node < N_NODES) {
            if (q < D / 4)
                v = *reinterpret_cast<const float4*>(out + (size_t)node * D + q * 4);
            else
                v = *reinterpret_cast<const float4*>(x + (size_t)node * D + (q - D / 4) * 4);
        }
        *reinterpret_cast<float4*>(As + r * BK + q * 4) = v;
    }
    __syncthreads();

    const int cg = t % (BN / TN);   // 0..15
    const int rg = t / (BN / TN);   // 0..15
    const int o0 = cg * TN;         // 0,6,...,90
    const int n0 = rg * TM;

    unsigned long long acc[TM][3];
    {
        unsigned long long b0 = *reinterpret_cast<const unsigned long long*>(bls + o0);
        unsigned long long b1 = *reinterpret_cast<const unsigned long long*>(bls + o0 + 2);
        unsigned long long b2 = *reinterpret_cast<const unsigned long long*>(bls + o0 + 4);
        #pragma unroll
        for (int i = 0; i < TM; i++) {
            acc[i][0] = b0; acc[i][1] = b1; acc[i][2] = b2;
        }
    }

    for (int k = 0; k < BK; k += 4) {
        float4 av[TM];
        #pragma unroll
        for (int i = 0; i < TM; i++)
            av[i] = *reinterpret_cast<const float4*>(As + (n0 + i) * BK + k);
        #pragma unroll
        for (int kk = 0; kk < 4; kk++) {
            const float* wr = Ws + (k + kk) * WPAD + o0;
            unsigned long long w0 = *reinterpret_cast<const unsigned long long*>(wr);
            unsigned long long w1 = *reinterpret_cast<const unsigned long long*>(wr + 2);
            unsigned long long w2 = *reinterpret_cast<const unsigned long long*>(wr + 4);
            #pragma unroll
            for (int i = 0; i < TM; i++) {
                float a = (kk == 0) ? av[i].x : (kk == 1) ? av[i].y
                        : (kk == 2) ? av[i].z : av[i].w;
                unsigned long long ap = dup2(a);
                fma2(acc[i][0], ap, w0);
                fma2(acc[i][1], ap, w1);
                fma2(acc[i][2], ap, w2);
            }
        }
    }

    // ---- epilogue: unpack, ReLU, store 3x float2 per row
    #pragma unroll
    for (int i = 0; i < TM; i++) {
        int node = rowBase + n0 + i;
        if (node >= N_NODES) continue;
        float* dst = out + (size_t)node * D + o0;
        #pragma unroll
        for (int j = 0; j < 3; j++) {
            float lo, hi;
            asm("mov.b64 {%0, %1}, %2;" : "=f"(lo), "=f"(hi) : "l"(acc[i][j]));
            float2 r = make_float2(fmaxf(lo, 0.f), fmaxf(hi, 0.f));
            *reinterpret_cast<float2*>(dst + 2 * j) = r;
        }
    }
}

// ---------------------------------------------------------------------------
extern "C" void kernel_launch(void* const* d_in, const int* in_sizes, int n_in,
                              void* d_out, int out_size) {
    const float* x  = (const float*)d_in[0];   // [N, 96]
    const int* ei   = (const int*)d_in[1];     // [2, E]
    const float* Wl = (const float*)d_in[2];   // [96, 96]
    const float* bl = (const float*)d_in[3];   // [96]
    const float* Wr = (const float*)d_in[4];   // [96, 96]
    float* out = (float*)d_out;                // [N, 96]

    cudaFuncSetAttribute(k_linear, cudaFuncAttributeMaxDynamicSharedMemorySize,
                         (int)SMEM_BYTES);

    void* cnt_ptr = nullptr;
    cudaGetSymbolAddress(&cnt_ptr, g_cnt);
    cudaMemsetAsync(cnt_ptr, 0, sizeof(int) * N_NODES);

    k_hist<<<(N_EDGES + 255) / 256, 256>>>(ei);
    k_scan<<<1, SCAN_T>>>();
    k_scatter<<<(N_EDGES + 255) / 256, 256>>>(ei);
    {
        int warps_per_block = 8;               // 256 threads
        int blocks = (N_NODES + warps_per_block - 1) / warps_per_block;
        k_agg<<<blocks, warps_per_block * 32>>>(x, out);
    }
    k_linear<<<(N_NODES + BM - 1) / BM, LTHREADS, SMEM_BYTES>>>(x, Wl, bl, Wr, out);
}

// round 8
// speedup vs baseline: 1.7118x; 1.3519x over previous
#include <cuda_runtime.h>
#include <cstdint>

#define N_NODES 50000
#define N_EDGES 800000
#define D 96
#define SCAN_TILE 1024
#define NB ((N_NODES + SCAN_TILE - 1) / SCAN_TILE)   // 49

typedef unsigned long long ull;

// ---------------- device scratch (no allocations allowed) -------------------
__device__ int g_cnt[N_NODES];       // per-dst degree (histogram)
__device__ int g_rowptr[N_NODES];    // block-LOCAL exclusive scan of degrees
__device__ int g_bsum[NB];           // per-scan-block totals
__device__ int g_bsumx[NB];          // exclusive scan of block totals
__device__ int g_rank[N_EDGES];      // within-dst rank of each edge
__device__ int g_csr_src[N_EDGES];   // src node per CSR slot

// true rowptr[i] = g_rowptr[i] + g_bsumx[i >> 10]

// ---------------- packed f32x2 helpers --------------------------------------
__device__ __forceinline__ ull dup2(float a) {
    ull r; asm("mov.b64 %0, {%1, %1};" : "=l"(r) : "f"(a)); return r;
}
__device__ __forceinline__ void fma2(ull& d, ull a, ull b) {
    asm("fma.rn.f32x2 %0, %1, %2, %0;" : "+l"(d) : "l"(a), "l"(b));
}
__device__ __forceinline__ void fadd2(ull& d, ull a) {
    asm("add.rn.f32x2 %0, %0, %1;" : "+l"(d) : "l"(a));
}
__device__ __forceinline__ ull fmul2(ull a, ull b) {
    ull r; asm("mul.rn.f32x2 %0, %1, %2;" : "=l"(r) : "l"(a), "l"(b)); return r;
}

// ---------------------------------------------------------------------------
// K1: histogram of dst degrees; atomicAdd return value = rank of edge in dst
// ---------------------------------------------------------------------------
__global__ void k_hist(const int* __restrict__ ei) {
    int e = blockIdx.x * blockDim.x + threadIdx.x;
    if (e >= N_EDGES) return;
    int dst = ei[N_EDGES + e];
    g_rank[e] = atomicAdd(&g_cnt[dst], 1);
}

// ---------------------------------------------------------------------------
// K2a: per-block (1024-node tile) local exclusive scan + block total
// ---------------------------------------------------------------------------
__global__ __launch_bounds__(256) void k_scan1() {
    __shared__ int wsum[8];
    const int blk = blockIdx.x, t = threadIdx.x;
    const int lane = t & 31, wid = t >> 5;
    int idx = blk * SCAN_TILE + t * 4;
    int v[4];
    #pragma unroll
    for (int i = 0; i < 4; i++)
        v[i] = (idx + i < N_NODES) ? g_cnt[idx + i] : 0;
    int tsum = v[0] + v[1] + v[2] + v[3];

    int incl = tsum;
    #pragma unroll
    for (int off = 1; off < 32; off <<= 1) {
        int s = __shfl_up_sync(0xffffffffu, incl, off);
        if (lane >= off) incl += s;
    }
    if (lane == 31) wsum[wid] = incl;
    __syncthreads();
    if (t == 0) {
        int s = 0;
        #pragma unroll
        for (int i = 0; i < 8; i++) { int x = wsum[i]; wsum[i] = s; s += x; }
        g_bsum[blk] = s;
    }
    __syncthreads();
    int excl = wsum[wid] + (incl - tsum);
    #pragma unroll
    for (int i = 0; i < 4; i++) {
        if (idx + i < N_NODES) g_rowptr[idx + i] = excl;
        excl += v[i];
    }
}

// ---------------------------------------------------------------------------
// K2b: tiny exclusive scan of NB block totals
// ---------------------------------------------------------------------------
__global__ void k_scan2() {
    __shared__ int s[NB];
    int t = threadIdx.x;
    if (t < NB) s[t] = g_bsum[t];
    __syncthreads();
    if (t == 0) {
        int a = 0;
        #pragma unroll
        for (int i = 0; i < NB; i++) { int x = s[i]; s[i] = a; a += x; }
    }
    __syncthreads();
    if (t < NB) g_bsumx[t] = s[t];
}

// ---------------------------------------------------------------------------
// K3: atomic-free scatter: slot = rowptr[dst] + bsumx[dst>>10] + rank[e]
// ---------------------------------------------------------------------------
__global__ void k_scatter(const int* __restrict__ ei) {
    int e = blockIdx.x * blockDim.x + threadIdx.x;
    if (e >= N_EDGES) return;
    int dst = ei[N_EDGES + e];
    int p = g_rowptr[dst] + g_bsumx[dst >> 10] + g_rank[e];
    g_csr_src[p] = ei[e];
}

// ---------------------------------------------------------------------------
// K4: warp-per-node mean aggregation, float4-per-lane (lanes 0..23), packed
//     f32x2 accumulate. Unroll 4 neighbors, dual accumulator banks.
// ---------------------------------------------------------------------------
__global__ void k_agg(const float* __restrict__ x, float* __restrict__ out) {
    int gw = (blockIdx.x * blockDim.x + threadIdx.x) >> 5;
    if (gw >= N_NODES) return;
    int lane = threadIdx.x & 31;
    int beg = g_rowptr[gw] + g_bsumx[gw >> 10];
    int end = (gw + 1 < N_NODES)
            ? (g_rowptr[gw + 1] + g_bsumx[(gw + 1) >> 10]) : N_EDGES;

    const bool act = lane < 24;
    const int col = lane * 4;     // cols [col, col+4) when act

    ull a0 = 0, a1 = 0, b0 = 0, b1 = 0;

    int j = beg;
    for (; j + 4 <= end; j += 4) {
        int s0 = __ldg(g_csr_src + j + 0);
        int s1 = __ldg(g_csr_src + j + 1);
        int s2 = __ldg(g_csr_src + j + 2);
        int s3 = __ldg(g_csr_src + j + 3);
        if (act) {
            ulonglong2 v0 = *reinterpret_cast<const ulonglong2*>(x + (size_t)s0 * D + col);
            ulonglong2 v1 = *reinterpret_cast<const ulonglong2*>(x + (size_t)s1 * D + col);
            ulonglong2 v2 = *reinterpret_cast<const ulonglong2*>(x + (size_t)s2 * D + col);
            ulonglong2 v3 = *reinterpret_cast<const ulonglong2*>(x + (size_t)s3 * D + col);
            fadd2(a0, v0.x); fadd2(a1, v0.y);
            fadd2(b0, v1.x); fadd2(b1, v1.y);
            fadd2(a0, v2.x); fadd2(a1, v2.y);
            fadd2(b0, v3.x); fadd2(b1, v3.y);
        }
    }
    for (; j < end; j++) {
        int s = __ldg(g_csr_src + j);
        if (act) {
            ulonglong2 v = *reinterpret_cast<const ulonglong2*>(x + (size_t)s * D + col);
            fadd2(a0, v.x); fadd2(a1, v.y);
        }
    }
    fadd2(a0, b0); fadd2(a1, b1);

    int deg = end - beg;
    float inv = (deg > 0) ? 1.0f / (float)deg : 0.0f;
    ull iv = dup2(inv);
    if (act) {
        ulonglong2 r;
        r.x = fmul2(a0, iv);
        r.y = fmul2(a1, iv);
        *reinterpret_cast<ulonglong2*>(out + (size_t)gw * D + col) = r;
    }
}

// ---------------------------------------------------------------------------
// K5: fused linear + ReLU, packed fma.rn.f32x2, split-K for 2 CTAs/SM.
//     C[50000 x 96] = relu([agg_mean | x] @ [Wl;Wr]_cols + bl)
//     BM=128, BN=96; K processed in two 96-halves reusing As[128x96] and
//     Ws[96x98]. 256 threads = 16 rowgroups x 16 colgroups, TM=8 x TN=6.
// ---------------------------------------------------------------------------
constexpr int BM = 128;
constexpr int BN = 96;
constexpr int TM = 8;
constexpr int TN = 6;
constexpr int LTHREADS = 256;
constexpr int WPAD = 98;
constexpr int SMEM_FLOATS = BM * D + D * WPAD + BN;   // 12288+9408+96
constexpr size_t SMEM_BYTES = (size_t)SMEM_FLOATS * sizeof(float);  // 87168 B

__global__ __launch_bounds__(LTHREADS, 2)
void k_linear(const float* __restrict__ x,
              const float* __restrict__ Wl,
              const float* __restrict__ bl,
              const float* __restrict__ Wr,
              float* __restrict__ out)   // agg_mean on entry, z on exit
{
    extern __shared__ float smem[];
    float* As  = smem;               // [BM][96]
    float* Ws  = smem + BM * D;      // [96][WPAD]
    float* bls = Ws + D * WPAD;      // [BN]

    const int t = threadIdx.x;
    const int rowBase = blockIdx.x * BM;
    if (t < BN) bls[t] = bl[t];

    const int cg = t & 15;        // 0..15
    const int rg = t >> 4;        // 0..15
    const int o0 = cg * TN;       // 0,6,...,90
    const int n0 = rg * TM;

    ull acc[TM][3];

    #pragma unroll
    for (int h = 0; h < 2; h++) {
        const float* W   = h ? Wr : Wl;
        const float* src = h ? x  : out;

        // stage Ws[k][o] = W[o][k] (coalesced LDG along k)
        for (int idx = t; idx < D * D; idx += LTHREADS) {
            int o = idx / D, k = idx - o * D;
            Ws[k * WPAD + o] = W[o * D + k];
        }
        // stage As rows
        for (int idx = t; idx < BM * (D / 4); idx += LTHREADS) {
            int r = idx / (D / 4), q = idx - r * (D / 4);
            int node = rowBase + r;
            float4 v = make_float4(0.f, 0.f, 0.f, 0.f);
            if (node < N_NODES)
                v = *reinterpret_cast<const float4*>(src + (size_t)node * D + q * 4);
            *reinterpret_cast<float4*>(As + r * D + q * 4) = v;
        }
        __syncthreads();

        if (h == 0) {
            ull b0 = *reinterpret_cast<const ull*>(bls + o0);
            ull b1 = *reinterpret_cast<const ull*>(bls + o0 + 2);
            ull b2 = *reinterpret_cast<const ull*>(bls + o0 + 4);
            #pragma unroll
            for (int i = 0; i < TM; i++) {
                acc[i][0] = b0; acc[i][1] = b1; acc[i][2] = b2;
            }
        }

        for (int k = 0; k < D; k += 4) {
            ull w[4][3];
            #pragma unroll
            for (int kk = 0; kk < 4; kk++) {
                const float* wr = Ws + (k + kk) * WPAD + o0;
                w[kk][0] = *reinterpret_cast<const ull*>(wr);
                w[kk][1] = *reinterpret_cast<const ull*>(wr + 2);
                w[kk][2] = *reinterpret_cast<const ull*>(wr + 4);
            }
            #pragma unroll
            for (int i = 0; i < TM; i++) {
                float4 av = *reinterpret_cast<const float4*>(As + (n0 + i) * D + k);
                ull ax = dup2(av.x), ay = dup2(av.y), az = dup2(av.z), aw = dup2(av.w);
                fma2(acc[i][0], ax, w[0][0]); fma2(acc[i][1], ax, w[0][1]); fma2(acc[i][2], ax, w[0][2]);
                fma2(acc[i][0], ay, w[1][0]); fma2(acc[i][1], ay, w[1][1]); fma2(acc[i][2], ay, w[1][2]);
                fma2(acc[i][0], az, w[2][0]); fma2(acc[i][1], az, w[2][1]); fma2(acc[i][2], az, w[2][2]);
                fma2(acc[i][0], aw, w[3][0]); fma2(acc[i][1], aw, w[3][1]); fma2(acc[i][2], aw, w[3][2]);
            }
        }
        __syncthreads();   // before next half restages (and before epilogue)
    }

    // epilogue: unpack, ReLU, store 3x float2 per row
    #pragma unroll
    for (int i = 0; i < TM; i++) {
        int node = rowBase + n0 + i;
        if (node >= N_NODES) continue;
        float* dst = out + (size_t)node * D + o0;
        #pragma unroll
        for (int j = 0; j < 3; j++) {
            float lo, hi;
            asm("mov.b64 {%0, %1}, %2;" : "=f"(lo), "=f"(hi) : "l"(acc[i][j]));
            float2 r = make_float2(fmaxf(lo, 0.f), fmaxf(hi, 0.f));
            *reinterpret_cast<float2*>(dst + 2 * j) = r;
        }
    }
}

// ---------------------------------------------------------------------------
extern "C" void kernel_launch(void* const* d_in, const int* in_sizes, int n_in,
                              void* d_out, int out_size) {
    const float* x  = (const float*)d_in[0];   // [N, 96]
    const int* ei   = (const int*)d_in[1];     // [2, E]
    const float* Wl = (const float*)d_in[2];   // [96, 96]
    const float* bl = (const float*)d_in[3];   // [96]
    const float* Wr = (const float*)d_in[4];   // [96, 96]
    float* out = (float*)d_out;                // [N, 96]

    cudaFuncSetAttribute(k_linear, cudaFuncAttributeMaxDynamicSharedMemorySize,
                         (int)SMEM_BYTES);

    void* cnt_ptr = nullptr;
    cudaGetSymbolAddress(&cnt_ptr, g_cnt);
    cudaMemsetAsync(cnt_ptr, 0, sizeof(int) * N_NODES);

    k_hist<<<(N_EDGES + 255) / 256, 256>>>(ei);
    k_scan1<<<NB, 256>>>();
    k_scan2<<<1, 64>>>();
    k_scatter<<<(N_EDGES + 255) / 256, 256>>>(ei);
    {
        int warps_per_block = 8;               // 256 threads
        int blocks = (N_NODES + warps_per_block - 1) / warps_per_block;
        k_agg<<<blocks, warps_per_block * 32>>>(x, out);
    }
    k_linear<<<(N_NODES + BM - 1) / BM, LTHREADS, SMEM_BYTES>>>(x, Wl, bl, Wr, out);
}